// round 6
// baseline (speedup 1.0000x reference)
#include <cuda_runtime.h>
#include <cstdint>

#define NMAX 100000
#define EMAX 1000000
#define LMAX 200000

// ---------------------------------------------------------------------------
// Static device scratch (allocation-free)
// ---------------------------------------------------------------------------
__device__ int    g_deg[NMAX];
__device__ float  g_dinv[NMAX];
__device__ int    g_off[NMAX];               // block-local exclusive scan
__device__ int    g_cur[NMAX];               // fill cursors
__device__ int    g_bsum[256];               // scan block sums (exclusive)
__device__ int    g_csr[EMAX];               // CSR: src node per slot
__device__ float4 g_h[(size_t)NMAX * 32];    // h = x@W (unscaled)
__device__ float4 g_x[(size_t)NMAX * 32];    // layer output
__device__ int    g_eidx[2 * EMAX];
__device__ int    g_lidx[2 * LMAX];
__device__ int    g_is64;

// ---------------------------------------------------------------------------
// f32x2 packed-FMA helpers (sm_103a dual-rate fp32 path)
// ---------------------------------------------------------------------------
__device__ __forceinline__ unsigned long long fma2(unsigned long long a,
                                                   unsigned long long b,
                                                   unsigned long long c) {
    unsigned long long d;
    asm("fma.rn.f32x2 %0, %1, %2, %3;" : "=l"(d) : "l"(a), "l"(b), "l"(c));
    return d;
}
__device__ __forceinline__ unsigned long long pack2(float lo, float hi) {
    unsigned long long o;
    asm("mov.b64 %0, {%1, %2};" : "=l"(o) : "f"(lo), "f"(hi));
    return o;
}
__device__ __forceinline__ void unpack2(unsigned long long v, float& lo, float& hi) {
    asm("mov.b64 {%0, %1}, %2;" : "=f"(lo), "=f"(hi) : "l"(v));
}

// ---------------------------------------------------------------------------
// init: dtype sniff (thread 0) + zero deg/cur
// ---------------------------------------------------------------------------
__global__ void k_init(const unsigned* __restrict__ w, int n) {
    int i = blockIdx.x * blockDim.x + threadIdx.x;
    if (i == 0) {
        int is64 = 1;
        for (int j = 0; j < 32; j++)
            if (w[2 * j + 1] != 0u) { is64 = 0; break; }
        g_is64 = is64;
    }
    if (i < n) { g_deg[i] = 0; g_cur[i] = 0; }
}

// ---------------------------------------------------------------------------
// GEMM device body: g_h[row] = X[row] @ W (unscaled)
// BM=128, BN=128(full), BK=32; 256 threads; 8x8/thread via f32x2
// ---------------------------------------------------------------------------
__device__ __forceinline__ void gemm_body(const float* __restrict__ X,
                                          const float* __restrict__ W,
                                          int n, int blockId,
                                          float (*As)[132], float (*Ws)[132]) {
    int tid = threadIdx.x;
    int tx = tid & 15;
    int ty = tid >> 4;
    int rowBase = blockId * 128;

    unsigned long long acc[8][4];
#pragma unroll
    for (int m = 0; m < 8; m++)
#pragma unroll
        for (int c = 0; c < 4; c++) acc[m][c] = 0ull;

    for (int kk = 0; kk < 128; kk += 32) {
#pragma unroll
        for (int i = 0; i < 4; i++) {
            int fi = tid + i * 256;
            int r = fi >> 3;
            int q = fi & 7;
            int row = rowBase + r;
            float4 v = make_float4(0.f, 0.f, 0.f, 0.f);
            if (row < n)
                v = *(const float4*)(X + (size_t)row * 128 + kk + q * 4);
            As[q * 4 + 0][r] = v.x;
            As[q * 4 + 1][r] = v.y;
            As[q * 4 + 2][r] = v.z;
            As[q * 4 + 3][r] = v.w;
        }
#pragma unroll
        for (int i = 0; i < 4; i++) {
            int fi = tid + i * 256;
            int k = fi >> 5;
            int q = fi & 31;
            float4 v = *(const float4*)(W + (size_t)(kk + k) * 128 + q * 4);
            *(float4*)&Ws[k][q * 4] = v;
        }
        __syncthreads();

#pragma unroll
        for (int k = 0; k < 32; k++) {
            float4 a0 = *(const float4*)&As[k][ty * 8];
            float4 a1 = *(const float4*)&As[k][ty * 8 + 4];
            unsigned long long ap[8];
            ap[0] = pack2(a0.x, a0.x); ap[1] = pack2(a0.y, a0.y);
            ap[2] = pack2(a0.z, a0.z); ap[3] = pack2(a0.w, a0.w);
            ap[4] = pack2(a1.x, a1.x); ap[5] = pack2(a1.y, a1.y);
            ap[6] = pack2(a1.z, a1.z); ap[7] = pack2(a1.w, a1.w);
            const unsigned long long* wp =
                (const unsigned long long*)&Ws[k][tx * 8];
            unsigned long long w0 = wp[0], w1 = wp[1], w2 = wp[2], w3 = wp[3];
#pragma unroll
            for (int m = 0; m < 8; m++) {
                acc[m][0] = fma2(ap[m], w0, acc[m][0]);
                acc[m][1] = fma2(ap[m], w1, acc[m][1]);
                acc[m][2] = fma2(ap[m], w2, acc[m][2]);
                acc[m][3] = fma2(ap[m], w3, acc[m][3]);
            }
        }
        __syncthreads();
    }

#pragma unroll
    for (int m = 0; m < 8; m++) {
        int row = rowBase + ty * 8 + m;
        if (row < n) {
            float4 v0, v1;
            unpack2(acc[m][0], v0.x, v0.y);
            unpack2(acc[m][1], v0.z, v0.w);
            unpack2(acc[m][2], v1.x, v1.y);
            unpack2(acc[m][3], v1.z, v1.w);
            g_h[(size_t)row * 32 + tx * 2 + 0] = v0;
            g_h[(size_t)row * 32 + tx * 2 + 1] = v1;
        }
    }
}

// ---------------------------------------------------------------------------
// fused kernel: blocks [0,gB) -> GEMM1; [gB,gB+eB) -> edge decode + degree
// histogram; [gB+eB, ...) -> label decode. All roles data-independent.
// ---------------------------------------------------------------------------
__global__ void __launch_bounds__(256)
k_fused(const float* __restrict__ X, const float* __restrict__ W,
        const void* __restrict__ eraw, const void* __restrict__ lraw,
        int n, int E, int L, int gB, int eB) {
    __shared__ float As[32][132];
    __shared__ float Ws[32][132];

    int bid = blockIdx.x;
    if (bid < gB) {
        gemm_body(X, W, n, bid, As, Ws);
        return;
    }
    int is64 = g_is64;
    int tid = threadIdx.x;
    if (bid < gB + eB) {
        // edge decode: 1024 elements per block
        int b = bid - gB;
        int twoE = 2 * E;
#pragma unroll
        for (int k = 0; k < 4; k++) {
            int i = b * 1024 + k * 256 + tid;
            if (i < twoE) {
                long long v = is64 ? ((const long long*)eraw)[i]
                                   : (long long)((const int*)eraw)[i];
                int x = (int)v;
                x = x < 0 ? 0 : (x >= n ? n - 1 : x);
                g_eidx[i] = x;
                if (i >= E) atomicAdd(&g_deg[x], 1);
            }
        }
    } else {
        // label decode
        int b = bid - gB - eB;
        int twoL = 2 * L;
#pragma unroll
        for (int k = 0; k < 4; k++) {
            int i = b * 1024 + k * 256 + tid;
            if (i < twoL) {
                long long v = is64 ? ((const long long*)lraw)[i]
                                   : (long long)((const int*)lraw)[i];
                int x = (int)v;
                x = x < 0 ? 0 : (x >= n ? n - 1 : x);
                g_lidx[i] = x;
            }
        }
    }
}

// standalone GEMM for layer 2 (input = g_x)
__global__ void __launch_bounds__(256)
k_gemm2(const float* __restrict__ W, int n) {
    __shared__ float As[32][132];
    __shared__ float Ws[32][132];
    gemm_body((const float*)g_x, W, n, blockIdx.x, As, Ws);
}

// ---------------------------------------------------------------------------
// scan (block-local exclusive) + dinv
// ---------------------------------------------------------------------------
__global__ void k_scan1(int n) {
    __shared__ int s[512];
    int t = threadIdx.x;
    int i = blockIdx.x * 512 + t;
    int v = (i < n) ? g_deg[i] : 0;
    if (i < n) g_dinv[i] = rsqrtf((float)v + 1.0f);
    s[t] = v;
    __syncthreads();
    for (int off = 1; off < 512; off <<= 1) {
        int add = (t >= off) ? s[t - off] : 0;
        __syncthreads();
        s[t] += add;
        __syncthreads();
    }
    if (i < n) g_off[i] = s[t] - v;
    if (t == 511) g_bsum[blockIdx.x] = s[511];
}

__global__ void k_scan2(int nb) {
    __shared__ int s[256];
    int t = threadIdx.x;
    int v = (t < nb) ? g_bsum[t] : 0;
    s[t] = v;
    __syncthreads();
    for (int off = 1; off < 256; off <<= 1) {
        int add = (t >= off) ? s[t - off] : 0;
        __syncthreads();
        s[t] += add;
        __syncthreads();
    }
    if (t < nb) g_bsum[t] = s[t] - v;
}

__global__ void k_fill(int E) {
    int i = blockIdx.x * blockDim.x + threadIdx.x;
    if (i >= E) return;
    int s = g_eidx[i];
    int d = g_eidx[E + i];
    int pos = g_off[d] + g_bsum[d >> 9] + atomicAdd(&g_cur[d], 1);
    g_csr[pos] = s;
}

// ---------------------------------------------------------------------------
// CSR pull aggregation + fused finalize:
// x[d] = act( dinv[d] * ( dinv[d]*h[d] + sum_s dinv[s]*h[s] ) + b )
// one warp per node, lane = float4 slice
// ---------------------------------------------------------------------------
__global__ void k_agg(const float* __restrict__ bias, int n, int do_relu) {
    int gw = (blockIdx.x * blockDim.x + threadIdx.x) >> 5;
    int lane = threadIdx.x & 31;
    if (gw >= n) return;
    int d = gw;

    float wd = g_dinv[d];
    float4 hd = g_h[(size_t)d * 32 + lane];
    float4 acc = make_float4(wd * hd.x, wd * hd.y, wd * hd.z, wd * hd.w);

    int o = g_off[d] + g_bsum[d >> 9];
    int c = g_deg[d];

    int j = 0;
    for (; j + 4 <= c; j += 4) {
        int s0 = g_csr[o + j + 0];
        int s1 = g_csr[o + j + 1];
        int s2 = g_csr[o + j + 2];
        int s3 = g_csr[o + j + 3];
        float w0 = g_dinv[s0], w1 = g_dinv[s1], w2 = g_dinv[s2], w3 = g_dinv[s3];
        float4 v0 = g_h[(size_t)s0 * 32 + lane];
        float4 v1 = g_h[(size_t)s1 * 32 + lane];
        float4 v2 = g_h[(size_t)s2 * 32 + lane];
        float4 v3 = g_h[(size_t)s3 * 32 + lane];
        acc.x = fmaf(w0, v0.x, fmaf(w1, v1.x, fmaf(w2, v2.x, fmaf(w3, v3.x, acc.x))));
        acc.y = fmaf(w0, v0.y, fmaf(w1, v1.y, fmaf(w2, v2.y, fmaf(w3, v3.y, acc.y))));
        acc.z = fmaf(w0, v0.z, fmaf(w1, v1.z, fmaf(w2, v2.z, fmaf(w3, v3.z, acc.z))));
        acc.w = fmaf(w0, v0.w, fmaf(w1, v1.w, fmaf(w2, v2.w, fmaf(w3, v3.w, acc.w))));
    }
    for (; j < c; j++) {
        int s = g_csr[o + j];
        float ws = g_dinv[s];
        float4 v = g_h[(size_t)s * 32 + lane];
        acc.x = fmaf(ws, v.x, acc.x);
        acc.y = fmaf(ws, v.y, acc.y);
        acc.z = fmaf(ws, v.z, acc.z);
        acc.w = fmaf(ws, v.w, acc.w);
    }

    float4 bv = ((const float4*)bias)[lane];
    float4 r = make_float4(fmaf(wd, acc.x, bv.x), fmaf(wd, acc.y, bv.y),
                           fmaf(wd, acc.z, bv.z), fmaf(wd, acc.w, bv.w));
    if (do_relu) {
        r.x = fmaxf(r.x, 0.f); r.y = fmaxf(r.y, 0.f);
        r.z = fmaxf(r.z, 0.f); r.w = fmaxf(r.w, 0.f);
    }
    g_x[(size_t)d * 32 + lane] = r;
}

// ---------------------------------------------------------------------------
// edge scoring: one warp per label edge, dot over 128 dims
// ---------------------------------------------------------------------------
__global__ void k_score(float* __restrict__ out, int L) {
    int gw = (blockIdx.x * blockDim.x + threadIdx.x) >> 5;
    int lane = threadIdx.x & 31;
    if (gw >= L) return;
    int u = g_lidx[gw];
    int v = g_lidx[L + gw];
    float4 xu = g_x[(size_t)u * 32 + lane];
    float4 xv = g_x[(size_t)v * 32 + lane];
    float p = xu.x * xv.x + xu.y * xv.y + xu.z * xv.z + xu.w * xv.w;
#pragma unroll
    for (int off = 16; off > 0; off >>= 1)
        p += __shfl_xor_sync(0xffffffffu, p, off);
    if (lane == 0) out[gw] = p;
}

// ---------------------------------------------------------------------------
extern "C" void kernel_launch(void* const* d_in, const int* in_sizes, int n_in,
                              void* d_out, int out_size) {
    const float* X   = (const float*)d_in[0];
    const void* eidx = d_in[1];
    const void* lidx = d_in[2];
    const float* W1  = (const float*)d_in[3];
    const float* b1  = (const float*)d_in[4];
    const float* W2  = (const float*)d_in[5];
    const float* b2  = (const float*)d_in[6];

    int N = in_sizes[0] / 128;
    int E = in_sizes[1] / 2;
    int L = in_sizes[2] / 2;
    int nb1 = (N + 511) / 512;

    int gB = (N + 127) / 128;            // GEMM tiles
    int eB = (2 * E + 1023) / 1024;      // edge-decode blocks
    int lB = (2 * L + 1023) / 1024;      // label-decode blocks

    // 1: init (zero + dtype sniff)
    k_init<<<(N + 255) / 256, 256>>>((const unsigned*)eidx, N);
    // 2: fused GEMM1 + edge/label decode (independent roles, one wave)
    k_fused<<<gB + eB + lB, 256>>>(X, W1, eidx, lidx, N, E, L, gB, eB);
    // 3-5: CSR build
    k_scan1<<<nb1, 512>>>(N);
    k_scan2<<<1, 256>>>(nb1);
    k_fill<<<(E + 255) / 256, 256>>>(E);
    // 6: layer-1 aggregate + relu
    k_agg<<<(N + 7) / 8, 256>>>(b1, N, 1);
    // 7: layer-2 GEMM
    k_gemm2<<<gB, 256>>>(W2, N);
    // 8: layer-2 aggregate
    k_agg<<<(N + 7) / 8, 256>>>(b2, N, 0);
    // 9: link scores
    k_score<<<(L + 7) / 8, 256>>>((float*)d_out, L);
}

// round 7
// speedup vs baseline: 1.2869x; 1.2869x over previous
#include <cuda_runtime.h>
#include <cuda_fp16.h>
#include <cstdint>

#define NMAX 100000
#define EMAX 1000000
#define LMAX 200000

// ---------------------------------------------------------------------------
// Static device scratch (allocation-free)
// ---------------------------------------------------------------------------
__device__ int     g_deg[NMAX];
__device__ float   g_dinv[NMAX];
__device__ int     g_off[NMAX];              // block-local exclusive scan
__device__ int     g_cur[NMAX];              // fill cursors
__device__ int     g_bsum[256];              // scan block sums (exclusive)
__device__ int     g_csr[EMAX];              // CSR: src node per slot
__device__ uint4   g_h[(size_t)NMAX * 16];   // h = x@W, fp16 (256 B/row)
__device__ float4  g_x[(size_t)NMAX * 32];   // layer-1 output, fp32 (GEMM2 input)
__device__ uint2   g_x2[(size_t)NMAX * 32];  // layer-2 output, fp16 (score input)
__device__ int     g_eidx[2 * EMAX];
__device__ int     g_lidx[2 * LMAX];
__device__ int     g_is64;

// ---------------------------------------------------------------------------
// f32x2 packed-FMA helpers (sm_103a dual-rate fp32 path)
// ---------------------------------------------------------------------------
__device__ __forceinline__ unsigned long long fma2(unsigned long long a,
                                                   unsigned long long b,
                                                   unsigned long long c) {
    unsigned long long d;
    asm("fma.rn.f32x2 %0, %1, %2, %3;" : "=l"(d) : "l"(a), "l"(b), "l"(c));
    return d;
}
__device__ __forceinline__ unsigned long long pack2(float lo, float hi) {
    unsigned long long o;
    asm("mov.b64 %0, {%1, %2};" : "=l"(o) : "f"(lo), "f"(hi));
    return o;
}
__device__ __forceinline__ void unpack2(unsigned long long v, float& lo, float& hi) {
    asm("mov.b64 {%0, %1}, %2;" : "=f"(lo), "=f"(hi) : "l"(v));
}

// ---------------------------------------------------------------------------
// init: dtype sniff (thread 0) + zero deg/cur
// ---------------------------------------------------------------------------
__global__ void k_init(const unsigned* __restrict__ w, int n) {
    int i = blockIdx.x * blockDim.x + threadIdx.x;
    if (i == 0) {
        int is64 = 1;
        for (int j = 0; j < 32; j++)
            if (w[2 * j + 1] != 0u) { is64 = 0; break; }
        g_is64 = is64;
    }
    if (i < n) { g_deg[i] = 0; g_cur[i] = 0; }
}

__global__ void k_cvt_lbl(const void* __restrict__ raw, int count, int n) {
    int i = blockIdx.x * blockDim.x + threadIdx.x;
    if (i >= count) return;
    long long v = g_is64 ? ((const long long*)raw)[i]
                         : (long long)((const int*)raw)[i];
    int x = (int)v;
    x = x < 0 ? 0 : (x >= n ? n - 1 : x);
    g_lidx[i] = x;
}

__global__ void k_cvt_edges(const void* __restrict__ raw, int twoE, int E, int n) {
    int i = blockIdx.x * blockDim.x + threadIdx.x;
    if (i >= twoE) return;
    long long v = g_is64 ? ((const long long*)raw)[i]
                         : (long long)((const int*)raw)[i];
    int x = (int)v;
    x = x < 0 ? 0 : (x >= n ? n - 1 : x);
    g_eidx[i] = x;
    if (i >= E) atomicAdd(&g_deg[x], 1);
}

// ---------------------------------------------------------------------------
// GEMM: g_h[row] = fp16( X[row] @ W )
// BM=128, BN=128(full), BK=32; 256 threads; 8x8/thread via f32x2
// ---------------------------------------------------------------------------
__global__ void __launch_bounds__(256)
k_gemm(const float* __restrict__ Xext, const float* __restrict__ W,
       int n, int use_internal) {
    const float* X = use_internal ? (const float*)g_x : Xext;

    __shared__ float As[32][132];
    __shared__ float Ws[32][132];

    int tid = threadIdx.x;
    int tx = tid & 15;              // cols tx*8 .. tx*8+7
    int ty = tid >> 4;              // rows ty*8 .. ty*8+7
    int rowBase = blockIdx.x * 128;

    unsigned long long acc[8][4];
#pragma unroll
    for (int m = 0; m < 8; m++)
#pragma unroll
        for (int c = 0; c < 4; c++) acc[m][c] = 0ull;

    for (int kk = 0; kk < 128; kk += 32) {
#pragma unroll
        for (int i = 0; i < 4; i++) {
            int fi = tid + i * 256;
            int r = fi >> 3;
            int q = fi & 7;
            int row = rowBase + r;
            float4 v = make_float4(0.f, 0.f, 0.f, 0.f);
            if (row < n)
                v = *(const float4*)(X + (size_t)row * 128 + kk + q * 4);
            As[q * 4 + 0][r] = v.x;
            As[q * 4 + 1][r] = v.y;
            As[q * 4 + 2][r] = v.z;
            As[q * 4 + 3][r] = v.w;
        }
#pragma unroll
        for (int i = 0; i < 4; i++) {
            int fi = tid + i * 256;
            int k = fi >> 5;
            int q = fi & 31;
            float4 v = *(const float4*)(W + (size_t)(kk + k) * 128 + q * 4);
            *(float4*)&Ws[k][q * 4] = v;
        }
        __syncthreads();

#pragma unroll
        for (int k = 0; k < 32; k++) {
            float4 a0 = *(const float4*)&As[k][ty * 8];
            float4 a1 = *(const float4*)&As[k][ty * 8 + 4];
            unsigned long long ap[8];
            ap[0] = pack2(a0.x, a0.x); ap[1] = pack2(a0.y, a0.y);
            ap[2] = pack2(a0.z, a0.z); ap[3] = pack2(a0.w, a0.w);
            ap[4] = pack2(a1.x, a1.x); ap[5] = pack2(a1.y, a1.y);
            ap[6] = pack2(a1.z, a1.z); ap[7] = pack2(a1.w, a1.w);
            const unsigned long long* wp =
                (const unsigned long long*)&Ws[k][tx * 8];
            unsigned long long w0 = wp[0], w1 = wp[1], w2 = wp[2], w3 = wp[3];
#pragma unroll
            for (int m = 0; m < 8; m++) {
                acc[m][0] = fma2(ap[m], w0, acc[m][0]);
                acc[m][1] = fma2(ap[m], w1, acc[m][1]);
                acc[m][2] = fma2(ap[m], w2, acc[m][2]);
                acc[m][3] = fma2(ap[m], w3, acc[m][3]);
            }
        }
        __syncthreads();
    }

#pragma unroll
    for (int m = 0; m < 8; m++) {
        int row = rowBase + ty * 8 + m;
        if (row < n) {
            float f0, f1, f2, f3, f4, f5, f6, f7;
            unpack2(acc[m][0], f0, f1);
            unpack2(acc[m][1], f2, f3);
            unpack2(acc[m][2], f4, f5);
            unpack2(acc[m][3], f6, f7);
            __half2 h0 = __floats2half2_rn(f0, f1);
            __half2 h1 = __floats2half2_rn(f2, f3);
            __half2 h2 = __floats2half2_rn(f4, f5);
            __half2 h3 = __floats2half2_rn(f6, f7);
            uint4 o;
            o.x = *(uint32_t*)&h0; o.y = *(uint32_t*)&h1;
            o.z = *(uint32_t*)&h2; o.w = *(uint32_t*)&h3;
            g_h[(size_t)row * 16 + tx] = o;  // 16 uint4 per row (256 B)
        }
    }
}

// ---------------------------------------------------------------------------
// scan (block-local exclusive) + dinv
// ---------------------------------------------------------------------------
__global__ void k_scan1(int n) {
    __shared__ int s[512];
    int t = threadIdx.x;
    int i = blockIdx.x * 512 + t;
    int v = (i < n) ? g_deg[i] : 0;
    if (i < n) g_dinv[i] = rsqrtf((float)v + 1.0f);
    s[t] = v;
    __syncthreads();
    for (int off = 1; off < 512; off <<= 1) {
        int add = (t >= off) ? s[t - off] : 0;
        __syncthreads();
        s[t] += add;
        __syncthreads();
    }
    if (i < n) g_off[i] = s[t] - v;
    if (t == 511) g_bsum[blockIdx.x] = s[511];
}

__global__ void k_scan2(int nb) {
    __shared__ int s[256];
    int t = threadIdx.x;
    int v = (t < nb) ? g_bsum[t] : 0;
    s[t] = v;
    __syncthreads();
    for (int off = 1; off < 256; off <<= 1) {
        int add = (t >= off) ? s[t - off] : 0;
        __syncthreads();
        s[t] += add;
        __syncthreads();
    }
    if (t < nb) g_bsum[t] = s[t] - v;
}

__global__ void k_fill(int E) {
    int i = blockIdx.x * blockDim.x + threadIdx.x;
    if (i >= E) return;
    int s = g_eidx[i];
    int d = g_eidx[E + i];
    int pos = g_off[d] + g_bsum[d >> 9] + atomicAdd(&g_cur[d], 1);
    g_csr[pos] = s;
}

// ---------------------------------------------------------------------------
// CSR pull aggregation + fused finalize (fp16 h gathers, fp32 accumulate):
// x[d] = act( dinv[d] * ( dinv[d]*h[d] + sum_s dinv[s]*h[s] ) + b )
// one warp per node; lane covers dims lane*4..lane*4+3 (one uint2 = 4 halves)
// out_half: 0 -> g_x (fp32, feeds GEMM2), 1 -> g_x2 (fp16, feeds score)
// ---------------------------------------------------------------------------
__device__ __forceinline__ void h_load4(int row, int lane, float4& f) {
    uint2 raw = ((const uint2*)g_h)[(size_t)row * 32 + lane];
    __half2 p0 = *(__half2*)&raw.x;
    __half2 p1 = *(__half2*)&raw.y;
    float2 a = __half22float2(p0);
    float2 b = __half22float2(p1);
    f.x = a.x; f.y = a.y; f.z = b.x; f.w = b.y;
}

__global__ void k_agg(const float* __restrict__ bias, int n,
                      int do_relu, int out_half) {
    int gw = (blockIdx.x * blockDim.x + threadIdx.x) >> 5;
    int lane = threadIdx.x & 31;
    if (gw >= n) return;
    int d = gw;

    float wd = g_dinv[d];
    float4 hd; h_load4(d, lane, hd);
    float4 acc = make_float4(wd * hd.x, wd * hd.y, wd * hd.z, wd * hd.w);

    int o = g_off[d] + g_bsum[d >> 9];
    int c = g_deg[d];

    int j = 0;
    for (; j + 4 <= c; j += 4) {
        int s0 = g_csr[o + j + 0];
        int s1 = g_csr[o + j + 1];
        int s2 = g_csr[o + j + 2];
        int s3 = g_csr[o + j + 3];
        float w0 = g_dinv[s0], w1 = g_dinv[s1], w2 = g_dinv[s2], w3 = g_dinv[s3];
        float4 v0, v1, v2, v3;
        h_load4(s0, lane, v0);
        h_load4(s1, lane, v1);
        h_load4(s2, lane, v2);
        h_load4(s3, lane, v3);
        acc.x = fmaf(w0, v0.x, fmaf(w1, v1.x, fmaf(w2, v2.x, fmaf(w3, v3.x, acc.x))));
        acc.y = fmaf(w0, v0.y, fmaf(w1, v1.y, fmaf(w2, v2.y, fmaf(w3, v3.y, acc.y))));
        acc.z = fmaf(w0, v0.z, fmaf(w1, v1.z, fmaf(w2, v2.z, fmaf(w3, v3.z, acc.z))));
        acc.w = fmaf(w0, v0.w, fmaf(w1, v1.w, fmaf(w2, v2.w, fmaf(w3, v3.w, acc.w))));
    }
    for (; j < c; j++) {
        int s = g_csr[o + j];
        float ws = g_dinv[s];
        float4 v; h_load4(s, lane, v);
        acc.x = fmaf(ws, v.x, acc.x);
        acc.y = fmaf(ws, v.y, acc.y);
        acc.z = fmaf(ws, v.z, acc.z);
        acc.w = fmaf(ws, v.w, acc.w);
    }

    float4 bv = ((const float4*)bias)[lane];
    float4 r = make_float4(fmaf(wd, acc.x, bv.x), fmaf(wd, acc.y, bv.y),
                           fmaf(wd, acc.z, bv.z), fmaf(wd, acc.w, bv.w));
    if (do_relu) {
        r.x = fmaxf(r.x, 0.f); r.y = fmaxf(r.y, 0.f);
        r.z = fmaxf(r.z, 0.f); r.w = fmaxf(r.w, 0.f);
    }
    if (out_half) {
        __half2 h0 = __floats2half2_rn(r.x, r.y);
        __half2 h1 = __floats2half2_rn(r.z, r.w);
        uint2 o2;
        o2.x = *(uint32_t*)&h0;
        o2.y = *(uint32_t*)&h1;
        g_x2[(size_t)d * 32 + lane] = o2;
    } else {
        g_x[(size_t)d * 32 + lane] = r;
    }
}

// ---------------------------------------------------------------------------
// edge scoring: one warp per label edge, fp16 gathers, fp32 dot over 128 dims
// ---------------------------------------------------------------------------
__global__ void k_score(float* __restrict__ out, int L) {
    int gw = (blockIdx.x * blockDim.x + threadIdx.x) >> 5;
    int lane = threadIdx.x & 31;
    if (gw >= L) return;
    int u = g_lidx[gw];
    int v = g_lidx[L + gw];
    uint2 ru = g_x2[(size_t)u * 32 + lane];
    uint2 rv = g_x2[(size_t)v * 32 + lane];
    float2 u0 = __half22float2(*(__half2*)&ru.x);
    float2 u1 = __half22float2(*(__half2*)&ru.y);
    float2 v0 = __half22float2(*(__half2*)&rv.x);
    float2 v1 = __half22float2(*(__half2*)&rv.y);
    float p = u0.x * v0.x + u0.y * v0.y + u1.x * v1.x + u1.y * v1.y;
#pragma unroll
    for (int off = 16; off > 0; off >>= 1)
        p += __shfl_xor_sync(0xffffffffu, p, off);
    if (lane == 0) out[gw] = p;
}

// ---------------------------------------------------------------------------
extern "C" void kernel_launch(void* const* d_in, const int* in_sizes, int n_in,
                              void* d_out, int out_size) {
    const float* X   = (const float*)d_in[0];
    const void* eidx = d_in[1];
    const void* lidx = d_in[2];
    const float* W1  = (const float*)d_in[3];
    const float* b1  = (const float*)d_in[4];
    const float* W2  = (const float*)d_in[5];
    const float* b2  = (const float*)d_in[6];

    int N = in_sizes[0] / 128;
    int E = in_sizes[1] / 2;
    int L = in_sizes[2] / 2;
    int nb1 = (N + 511) / 512;
    int gemmBlocks = (N + 127) / 128;

    // Serial pipeline (R3-proven structure; fusion/stream variants regressed).
    k_init<<<(N + 255) / 256, 256>>>((const unsigned*)eidx, N);       // 1
    k_cvt_lbl<<<(2 * L + 255) / 256, 256>>>(lidx, 2 * L, N);          // 2
    k_cvt_edges<<<(2 * E + 255) / 256, 256>>>(eidx, 2 * E, E, N);     // 3
    k_gemm<<<gemmBlocks, 256>>>(X, W1, N, 0);                         // 4 <- ncu
    k_scan1<<<nb1, 512>>>(N);                                         // 5
    k_scan2<<<1, 256>>>(nb1);                                         // 6
    k_fill<<<(E + 255) / 256, 256>>>(E);                              // 7
    k_agg<<<(N + 7) / 8, 256>>>(b1, N, 1, 0);                         // 8
    k_gemm<<<gemmBlocks, 256>>>(X, W2, N, 1);                         // 9
    k_agg<<<(N + 7) / 8, 256>>>(b2, N, 0, 1);                         // 10
    k_score<<<(L + 7) / 8, 256>>>((float*)d_out, L);                  // 11
}

// round 8
// speedup vs baseline: 1.3242x; 1.0289x over previous
#include <cuda_runtime.h>
#include <cuda_fp16.h>
#include <cstdint>

#define NMAX 100000
#define EMAX 1000000
#define LMAX 200000

// ---------------------------------------------------------------------------
// Static device scratch (allocation-free)
// ---------------------------------------------------------------------------
__device__ int     g_deg[NMAX];
__device__ float   g_dinv[NMAX];
__device__ int     g_off[NMAX];              // block-local exclusive scan
__device__ int     g_cur[NMAX];              // fill cursors
__device__ int     g_bsum[256];              // scan block sums (exclusive)
__device__ int     g_csr[EMAX];              // CSR: src node per slot
__device__ uint4   g_h[(size_t)NMAX * 16];   // h = x@W, fp16 (256 B/row)
__device__ float4  g_x[(size_t)NMAX * 32];   // layer-1 output, fp32 (GEMM2 input)
__device__ uint2   g_x2[(size_t)NMAX * 32];  // layer-2 output, fp16 (score input)
__device__ int     g_eidx[2 * EMAX];
__device__ int     g_lidx[2 * LMAX];
__device__ int     g_is64;

// ---------------------------------------------------------------------------
// f32x2 packed-FMA helpers (sm_103a dual-rate fp32 path)
// ---------------------------------------------------------------------------
__device__ __forceinline__ unsigned long long fma2(unsigned long long a,
                                                   unsigned long long b,
                                                   unsigned long long c) {
    unsigned long long d;
    asm("fma.rn.f32x2 %0, %1, %2, %3;" : "=l"(d) : "l"(a), "l"(b), "l"(c));
    return d;
}
__device__ __forceinline__ unsigned long long pack2(float lo, float hi) {
    unsigned long long o;
    asm("mov.b64 %0, {%1, %2};" : "=l"(o) : "f"(lo), "f"(hi));
    return o;
}
__device__ __forceinline__ void unpack2(unsigned long long v, float& lo, float& hi) {
    asm("mov.b64 {%0, %1}, %2;" : "=f"(lo), "=f"(hi) : "l"(v));
}

// ---------------------------------------------------------------------------
// init: dtype sniff (thread 0) + zero deg/cur
// ---------------------------------------------------------------------------
__global__ void k_init(const unsigned* __restrict__ w, int n) {
    int i = blockIdx.x * blockDim.x + threadIdx.x;
    if (i == 0) {
        int is64 = 1;
        for (int j = 0; j < 32; j++)
            if (w[2 * j + 1] != 0u) { is64 = 0; break; }
        g_is64 = is64;
    }
    if (i < n) { g_deg[i] = 0; g_cur[i] = 0; }
}

__global__ void k_cvt_lbl(const void* __restrict__ raw, int count, int n) {
    int i = blockIdx.x * blockDim.x + threadIdx.x;
    if (i >= count) return;
    long long v = g_is64 ? ((const long long*)raw)[i]
                         : (long long)((const int*)raw)[i];
    int x = (int)v;
    x = x < 0 ? 0 : (x >= n ? n - 1 : x);
    g_lidx[i] = x;
}

__global__ void k_cvt_edges(const void* __restrict__ raw, int twoE, int E, int n) {
    int i = blockIdx.x * blockDim.x + threadIdx.x;
    if (i >= twoE) return;
    long long v = g_is64 ? ((const long long*)raw)[i]
                         : (long long)((const int*)raw)[i];
    int x = (int)v;
    x = x < 0 ? 0 : (x >= n ? n - 1 : x);
    g_eidx[i] = x;
    if (i >= E) atomicAdd(&g_deg[x], 1);
}

// ---------------------------------------------------------------------------
// GEMM: g_h[row] = fp16( X[row] @ W )
// BM=128, BN=128, BK=32; 128 threads; 16Mx8N per thread, M-paired f32x2 acc.
// A-pairs load as direct LDS.64 (no packing); only W needs pack2 (8/k).
// ---------------------------------------------------------------------------
__global__ void __launch_bounds__(128)
k_gemm(const float* __restrict__ Xext, const float* __restrict__ W,
       int n, int use_internal) {
    const float* X = use_internal ? (const float*)g_x : Xext;

    __shared__ float As[32][132];   // [k][row], row-pairs 8B aligned
    __shared__ float Ws[32][132];   // [k][col]

    int tid = threadIdx.x;
    int tx = tid & 15;              // 16 col groups: cols tx*8 .. tx*8+7
    int ty = tid >> 4;              // 8 row groups: rows ty*16 .. ty*16+15
    int rowBase = blockIdx.x * 128;

    unsigned long long acc[8][8];   // [m-pair][col]; lanes = (row 2m, row 2m+1)
#pragma unroll
    for (int m = 0; m < 8; m++)
#pragma unroll
        for (int c = 0; c < 8; c++) acc[m][c] = 0ull;

    for (int kk = 0; kk < 128; kk += 32) {
        // load A tile: 128 rows x 32 k -> transposed smem [k][row]
#pragma unroll
        for (int i = 0; i < 8; i++) {
            int fi = tid + i * 128;       // 0..1023 float4 slots
            int r = fi >> 3;              // row in tile
            int q = fi & 7;               // float4 group along k
            int row = rowBase + r;
            float4 v = make_float4(0.f, 0.f, 0.f, 0.f);
            if (row < n)
                v = *(const float4*)(X + (size_t)row * 128 + kk + q * 4);
            As[q * 4 + 0][r] = v.x;
            As[q * 4 + 1][r] = v.y;
            As[q * 4 + 2][r] = v.z;
            As[q * 4 + 3][r] = v.w;
        }
        // load W tile: 32 k x 128 cols
#pragma unroll
        for (int i = 0; i < 8; i++) {
            int fi = tid + i * 128;       // 0..1023
            int k = fi >> 5;
            int q = fi & 31;
            float4 v = *(const float4*)(W + (size_t)(kk + k) * 128 + q * 4);
            *(float4*)&Ws[k][q * 4] = v;
        }
        __syncthreads();

#pragma unroll
        for (int k = 0; k < 32; k++) {
            // A: 8 M-pairs as direct u64 loads (adjacent rows)
            unsigned long long ap[8];
            const unsigned long long* apt =
                (const unsigned long long*)&As[k][ty * 16];
#pragma unroll
            for (int m = 0; m < 8; m++) ap[m] = apt[m];
            // W: 8 cols, duplicated into f32x2 lanes
            float4 w0 = *(const float4*)&Ws[k][tx * 8];
            float4 w1 = *(const float4*)&Ws[k][tx * 8 + 4];
            unsigned long long wd[8];
            wd[0] = pack2(w0.x, w0.x); wd[1] = pack2(w0.y, w0.y);
            wd[2] = pack2(w0.z, w0.z); wd[3] = pack2(w0.w, w0.w);
            wd[4] = pack2(w1.x, w1.x); wd[5] = pack2(w1.y, w1.y);
            wd[6] = pack2(w1.z, w1.z); wd[7] = pack2(w1.w, w1.w);
#pragma unroll
            for (int m = 0; m < 8; m++)
#pragma unroll
                for (int c = 0; c < 8; c++)
                    acc[m][c] = fma2(ap[m], wd[c], acc[m][c]);
        }
        __syncthreads();
    }

    // epilogue: each m-pair holds rows (2m, 2m+1) for cols tx*8..+7
#pragma unroll
    for (int m = 0; m < 8; m++) {
        int row0 = rowBase + ty * 16 + 2 * m;
        float e[8], o[8];
#pragma unroll
        for (int c = 0; c < 8; c++) unpack2(acc[m][c], e[c], o[c]);
        if (row0 < n) {
            __half2 h0 = __floats2half2_rn(e[0], e[1]);
            __half2 h1 = __floats2half2_rn(e[2], e[3]);
            __half2 h2 = __floats2half2_rn(e[4], e[5]);
            __half2 h3 = __floats2half2_rn(e[6], e[7]);
            uint4 ov;
            ov.x = *(uint32_t*)&h0; ov.y = *(uint32_t*)&h1;
            ov.z = *(uint32_t*)&h2; ov.w = *(uint32_t*)&h3;
            g_h[(size_t)row0 * 16 + tx] = ov;
        }
        if (row0 + 1 < n) {
            __half2 h0 = __floats2half2_rn(o[0], o[1]);
            __half2 h1 = __floats2half2_rn(o[2], o[3]);
            __half2 h2 = __floats2half2_rn(o[4], o[5]);
            __half2 h3 = __floats2half2_rn(o[6], o[7]);
            uint4 ov;
            ov.x = *(uint32_t*)&h0; ov.y = *(uint32_t*)&h1;
            ov.z = *(uint32_t*)&h2; ov.w = *(uint32_t*)&h3;
            g_h[(size_t)(row0 + 1) * 16 + tx] = ov;
        }
    }
}

// ---------------------------------------------------------------------------
// scan (block-local exclusive) + dinv
// ---------------------------------------------------------------------------
__global__ void k_scan1(int n) {
    __shared__ int s[512];
    int t = threadIdx.x;
    int i = blockIdx.x * 512 + t;
    int v = (i < n) ? g_deg[i] : 0;
    if (i < n) g_dinv[i] = rsqrtf((float)v + 1.0f);
    s[t] = v;
    __syncthreads();
    for (int off = 1; off < 512; off <<= 1) {
        int add = (t >= off) ? s[t - off] : 0;
        __syncthreads();
        s[t] += add;
        __syncthreads();
    }
    if (i < n) g_off[i] = s[t] - v;
    if (t == 511) g_bsum[blockIdx.x] = s[511];
}

__global__ void k_scan2(int nb) {
    __shared__ int s[256];
    int t = threadIdx.x;
    int v = (t < nb) ? g_bsum[t] : 0;
    s[t] = v;
    __syncthreads();
    for (int off = 1; off < 256; off <<= 1) {
        int add = (t >= off) ? s[t - off] : 0;
        __syncthreads();
        s[t] += add;
        __syncthreads();
    }
    if (t < nb) g_bsum[t] = s[t] - v;
}

__global__ void k_fill(int E) {
    int i = blockIdx.x * blockDim.x + threadIdx.x;
    if (i >= E) return;
    int s = g_eidx[i];
    int d = g_eidx[E + i];
    int pos = g_off[d] + g_bsum[d >> 9] + atomicAdd(&g_cur[d], 1);
    g_csr[pos] = s;
}

// ---------------------------------------------------------------------------
// CSR pull aggregation + fused finalize (fp16 h gathers, fp32 accumulate):
// x[d] = act( dinv[d] * ( dinv[d]*h[d] + sum_s dinv[s]*h[s] ) + b )
// one warp per node; lane covers dims lane*4..lane*4+3
// ---------------------------------------------------------------------------
__device__ __forceinline__ void h_load4(int row, int lane, float4& f) {
    uint2 raw = ((const uint2*)g_h)[(size_t)row * 32 + lane];
    __half2 p0 = *(__half2*)&raw.x;
    __half2 p1 = *(__half2*)&raw.y;
    float2 a = __half22float2(p0);
    float2 b = __half22float2(p1);
    f.x = a.x; f.y = a.y; f.z = b.x; f.w = b.y;
}

__global__ void k_agg(const float* __restrict__ bias, int n,
                      int do_relu, int out_half) {
    int gw = (blockIdx.x * blockDim.x + threadIdx.x) >> 5;
    int lane = threadIdx.x & 31;
    if (gw >= n) return;
    int d = gw;

    float wd = g_dinv[d];
    float4 hd; h_load4(d, lane, hd);
    float4 acc = make_float4(wd * hd.x, wd * hd.y, wd * hd.z, wd * hd.w);

    int o = g_off[d] + g_bsum[d >> 9];
    int c = g_deg[d];

    int j = 0;
    for (; j + 4 <= c; j += 4) {
        int s0 = g_csr[o + j + 0];
        int s1 = g_csr[o + j + 1];
        int s2 = g_csr[o + j + 2];
        int s3 = g_csr[o + j + 3];
        float w0 = g_dinv[s0], w1 = g_dinv[s1], w2 = g_dinv[s2], w3 = g_dinv[s3];
        float4 v0, v1, v2, v3;
        h_load4(s0, lane, v0);
        h_load4(s1, lane, v1);
        h_load4(s2, lane, v2);
        h_load4(s3, lane, v3);
        acc.x = fmaf(w0, v0.x, fmaf(w1, v1.x, fmaf(w2, v2.x, fmaf(w3, v3.x, acc.x))));
        acc.y = fmaf(w0, v0.y, fmaf(w1, v1.y, fmaf(w2, v2.y, fmaf(w3, v3.y, acc.y))));
        acc.z = fmaf(w0, v0.z, fmaf(w1, v1.z, fmaf(w2, v2.z, fmaf(w3, v3.z, acc.z))));
        acc.w = fmaf(w0, v0.w, fmaf(w1, v1.w, fmaf(w2, v2.w, fmaf(w3, v3.w, acc.w))));
    }
    for (; j < c; j++) {
        int s = g_csr[o + j];
        float ws = g_dinv[s];
        float4 v; h_load4(s, lane, v);
        acc.x = fmaf(ws, v.x, acc.x);
        acc.y = fmaf(ws, v.y, acc.y);
        acc.z = fmaf(ws, v.z, acc.z);
        acc.w = fmaf(ws, v.w, acc.w);
    }

    float4 bv = ((const float4*)bias)[lane];
    float4 r = make_float4(fmaf(wd, acc.x, bv.x), fmaf(wd, acc.y, bv.y),
                           fmaf(wd, acc.z, bv.z), fmaf(wd, acc.w, bv.w));
    if (do_relu) {
        r.x = fmaxf(r.x, 0.f); r.y = fmaxf(r.y, 0.f);
        r.z = fmaxf(r.z, 0.f); r.w = fmaxf(r.w, 0.f);
    }
    if (out_half) {
        __half2 h0 = __floats2half2_rn(r.x, r.y);
        __half2 h1 = __floats2half2_rn(r.z, r.w);
        uint2 o2;
        o2.x = *(uint32_t*)&h0;
        o2.y = *(uint32_t*)&h1;
        g_x2[(size_t)d * 32 + lane] = o2;
    } else {
        g_x[(size_t)d * 32 + lane] = r;
    }
}

// ---------------------------------------------------------------------------
// edge scoring: one warp per label edge, fp16 gathers, fp32 dot over 128 dims
// ---------------------------------------------------------------------------
__global__ void k_score(float* __restrict__ out, int L) {
    int gw = (blockIdx.x * blockDim.x + threadIdx.x) >> 5;
    int lane = threadIdx.x & 31;
    if (gw >= L) return;
    int u = g_lidx[gw];
    int v = g_lidx[L + gw];
    uint2 ru = g_x2[(size_t)u * 32 + lane];
    uint2 rv = g_x2[(size_t)v * 32 + lane];
    float2 u0 = __half22float2(*(__half2*)&ru.x);
    float2 u1 = __half22float2(*(__half2*)&ru.y);
    float2 v0 = __half22float2(*(__half2*)&rv.x);
    float2 v1 = __half22float2(*(__half2*)&rv.y);
    float p = u0.x * v0.x + u0.y * v0.y + u1.x * v1.x + u1.y * v1.y;
#pragma unroll
    for (int off = 16; off > 0; off >>= 1)
        p += __shfl_xor_sync(0xffffffffu, p, off);
    if (lane == 0) out[gw] = p;
}

// ---------------------------------------------------------------------------
extern "C" void kernel_launch(void* const* d_in, const int* in_sizes, int n_in,
                              void* d_out, int out_size) {
    const float* X   = (const float*)d_in[0];
    const void* eidx = d_in[1];
    const void* lidx = d_in[2];
    const float* W1  = (const float*)d_in[3];
    const float* b1  = (const float*)d_in[4];
    const float* W2  = (const float*)d_in[5];
    const float* b2  = (const float*)d_in[6];

    int N = in_sizes[0] / 128;
    int E = in_sizes[1] / 2;
    int L = in_sizes[2] / 2;
    int nb1 = (N + 511) / 512;
    int gemmBlocks = (N + 127) / 128;

    // Serial pipeline (proven structure; stream/role fusion regressed).
    k_init<<<(N + 255) / 256, 256>>>((const unsigned*)eidx, N);       // 1
    k_cvt_lbl<<<(2 * L + 255) / 256, 256>>>(lidx, 2 * L, N);          // 2
    k_cvt_edges<<<(2 * E + 255) / 256, 256>>>(eidx, 2 * E, E, N);     // 3
    k_gemm<<<gemmBlocks, 128>>>(X, W1, N, 0);                         // 4 <- ncu
    k_scan1<<<nb1, 512>>>(N);                                         // 5
    k_scan2<<<1, 256>>>(nb1);                                         // 6
    k_fill<<<(E + 255) / 256, 256>>>(E);                              // 7
    k_agg<<<(N + 7) / 8, 256>>>(b1, N, 1, 0);                         // 8
    k_gemm<<<gemmBlocks, 128>>>(X, W2, N, 1);                         // 9
    k_agg<<<(N + 7) / 8, 256>>>(b2, N, 0, 1);                         // 10
    k_score<<<(L + 7) / 8, 256>>>((float*)d_out, L);                  // 11
}